// round 1
// baseline (speedup 1.0000x reference)
#include <cuda_runtime.h>
#include <cstdint>

#define BB 256
#define SS 512
#define N_IN 2048
#define N_OUT 512
#define HH 30
#define ROWS (BB*SS)   // 131072

// ---------------- device scratch (no allocation allowed) ----------------
__device__ float g_flat[(size_t)ROWS * HH];   // fc1 output (post-ReLU), 15.7 MB
__device__ float g_partial[512 * 64];         // per-block BN partial sums/sumsq
__device__ float g_mu[HH];
__device__ float g_rstd[HH];

// ---------------- fc1: [131072,2048] @ [2048,30] + bias + ReLU + BN partials --
#define FC1_TM 256
#define FC1_KC 16
#define FC1_THREADS 192

__global__ __launch_bounds__(FC1_THREADS)
void fc1_kernel(const float* __restrict__ x, const float* __restrict__ W1,
                const float* __restrict__ b1)
{
    __shared__ __align__(16) float xs[FC1_KC][FC1_TM];  // [k][row]
    __shared__ __align__(16) float ws[FC1_KC][32];      // [k][col]
    __shared__ float red[2][HH][33];

    const int tid = threadIdx.x;           // 0..191
    const int rg  = tid / 6;               // 0..31
    const int cg  = tid % 6;               // 0..5
    const int r0  = rg * 8;
    const int c0  = cg * 5;
    const size_t rowBase = (size_t)blockIdx.x * FC1_TM;

    float acc[8][5];
    #pragma unroll
    for (int i = 0; i < 8; i++)
        #pragma unroll
        for (int j = 0; j < 5; j++) acc[i][j] = 0.f;

    for (int kc = 0; kc < N_IN; kc += FC1_KC) {
        // load x tile (256 rows x 16 k) as float4 along k
        for (int i = tid; i < FC1_TM * FC1_KC / 4; i += FC1_THREADS) {
            int r  = i >> 2;
            int k4 = i & 3;
            float4 v = *(const float4*)&x[(rowBase + r) * (size_t)N_IN + kc + k4 * 4];
            xs[k4*4+0][r] = v.x; xs[k4*4+1][r] = v.y;
            xs[k4*4+2][r] = v.z; xs[k4*4+3][r] = v.w;
        }
        // load W1 tile (16 x 30)
        for (int i = tid; i < FC1_KC * HH; i += FC1_THREADS) {
            int k = i / HH, c = i % HH;
            ws[k][c] = W1[(size_t)(kc + k) * HH + c];
        }
        __syncthreads();
        #pragma unroll
        for (int k = 0; k < FC1_KC; k++) {
            float4 xv0 = *(const float4*)&xs[k][r0];
            float4 xv1 = *(const float4*)&xs[k][r0 + 4];
            float xv[8] = {xv0.x, xv0.y, xv0.z, xv0.w, xv1.x, xv1.y, xv1.z, xv1.w};
            float wv[5];
            #pragma unroll
            for (int j = 0; j < 5; j++) wv[j] = ws[k][c0 + j];
            #pragma unroll
            for (int i = 0; i < 8; i++)
                #pragma unroll
                for (int j = 0; j < 5; j++) acc[i][j] += xv[i] * wv[j];
        }
        __syncthreads();
    }

    // bias + ReLU + store + per-thread BN partials
    float bloc[5];
    #pragma unroll
    for (int j = 0; j < 5; j++) bloc[j] = b1[c0 + j];
    float psum[5] = {0,0,0,0,0}, psq[5] = {0,0,0,0,0};
    #pragma unroll
    for (int i = 0; i < 8; i++) {
        size_t row = rowBase + r0 + i;
        #pragma unroll
        for (int j = 0; j < 5; j++) {
            float v = acc[i][j] + bloc[j];
            v = fmaxf(v, 0.f);
            g_flat[row * HH + c0 + j] = v;
            psum[j] += v;
            psq[j]  += v * v;
        }
    }
    #pragma unroll
    for (int j = 0; j < 5; j++) {
        red[0][c0 + j][rg] = psum[j];
        red[1][c0 + j][rg] = psq[j];
    }
    __syncthreads();
    if (tid < HH) {
        float s = 0.f, q = 0.f;
        #pragma unroll 8
        for (int g = 0; g < 32; g++) { s += red[0][tid][g]; q += red[1][tid][g]; }
        g_partial[blockIdx.x * 60 + tid]      = s;
        g_partial[blockIdx.x * 60 + 30 + tid] = q;
    }
}

// ---------------- BN finalize (1 block) ----------------
__global__ void bn_stats_kernel()
{
    int c = threadIdx.x;
    if (c < HH) {
        float s = 0.f, q = 0.f;
        for (int p = 0; p < 512; p++) {
            s += g_partial[p * 60 + c];
            q += g_partial[p * 60 + 30 + c];
        }
        const float n = (float)ROWS;
        float mu  = s / n;
        float var = q / n - mu * mu;           // biased variance (PyTorch BN train)
        g_mu[c]   = mu;
        g_rstd[c] = rsqrtf(var + 1e-5f);
    }
}

// ---------------- LSTM: 1 block / batch element, layer1 pipelined 1 step behind
#define LSTM_THREADS 256
#define LSTM_SMEM_FLOATS (SS*32 + 32 + 32 + 32 + 128 + 128 + 32 + 32)
#define LSTM_SMEM_BYTES  (LSTM_SMEM_FLOATS * 4)

__device__ __forceinline__ float fsig(float v) {
    return __fdividef(1.f, 1.f + __expf(-v));
}
__device__ __forceinline__ float ftanh(float v) {
    // 2*sigmoid(2v)-1; saturates cleanly for |v| large (expf -> 0/inf)
    return 2.f * fsig(2.f * v) - 1.f;
}

__device__ __forceinline__ float dot_step(const float* __restrict__ xv,
                                          const float* __restrict__ hv,
                                          const float (&wi)[32], const float (&wh)[32],
                                          float bj)
{
    const float4* x4 = (const float4*)xv;
    const float4* h4 = (const float4*)hv;
    float a0 = bj, a1 = 0.f, a2 = 0.f, a3 = 0.f;
    #pragma unroll
    for (int q = 0; q < 8; q++) {
        float4 xq = x4[q];
        a0 += wi[4*q+0] * xq.x; a1 += wi[4*q+1] * xq.y;
        a2 += wi[4*q+2] * xq.z; a3 += wi[4*q+3] * xq.w;
    }
    #pragma unroll
    for (int q = 0; q < 8; q++) {
        float4 hq = h4[q];
        a0 += wh[4*q+0] * hq.x; a1 += wh[4*q+1] * hq.y;
        a2 += wh[4*q+2] * hq.z; a3 += wh[4*q+3] * hq.w;
    }
    return (a0 + a1) + (a2 + a3);
}

__global__ __launch_bounds__(LSTM_THREADS, 2)
void lstm_kernel(const float* __restrict__ h0, const float* __restrict__ c0,
                 const float* __restrict__ Wih0, const float* __restrict__ Whh0,
                 const float* __restrict__ bias0,
                 const float* __restrict__ Wih1, const float* __restrict__ Whh1,
                 const float* __restrict__ bias1,
                 float* __restrict__ rnn_out)
{
    extern __shared__ __align__(16) float lsm[];
    float* xs    = lsm;                    // [512][32] normalized inputs (cols 30,31 = 0)
    float* h0s   = lsm + SS * 32;          // [32]
    float* h1s   = h0s + 32;               // [32]
    float* y0s   = h1s + 32;               // [32]
    float* z0s   = y0s + 32;               // [128] (120 used)
    float* z1s   = z0s + 128;              // [128]
    float* mus   = z1s + 128;              // [32]
    float* rstds = mus + 32;               // [32]

    const int tid = threadIdx.x;
    const int b   = blockIdx.x;

    if (tid < 32) {
        mus[tid]   = (tid < HH) ? g_mu[tid]   : 0.f;
        rstds[tid] = (tid < HH) ? g_rstd[tid] : 0.f;
        h0s[tid] = (tid < HH) ? h0[b * HH + tid]            : 0.f;
        h1s[tid] = (tid < HH) ? h0[BB * HH + b * HH + tid]  : 0.f;
        y0s[tid] = 0.f;
    }
    __syncthreads();

    // stage + normalize the whole input sequence for this batch element
    const float* fb = g_flat + (size_t)b * (SS * HH);
    for (int i = tid; i < SS * 32; i += LSTM_THREADS) {
        int s = i >> 5, k = i & 31;
        xs[i] = (k < HH) ? (fb[s * HH + k] - mus[k]) * rstds[k] : 0.f;
    }

    // weights into registers (padded to 32 with zeros)
    float wi[32], wh[32];
    float bj = 0.f;
    #pragma unroll
    for (int k = 0; k < 32; k++) { wi[k] = 0.f; wh[k] = 0.f; }
    if (tid < 120) {
        #pragma unroll
        for (int k = 0; k < HH; k++) {
            wi[k] = Wih0[tid * HH + k];
            wh[k] = Whh0[tid * HH + k];
        }
        bj = bias0[tid];
    } else if (tid >= 128 && tid < 248) {
        int j = tid - 128;
        #pragma unroll
        for (int k = 0; k < HH; k++) {
            wi[k] = Wih1[j * HH + k];
            wh[k] = Whh1[j * HH + k];
        }
        bj = bias1[j];
    }

    float creg = 0.f;
    if (tid < HH)                         creg = c0[b * HH + tid];
    else if (tid >= 128 && tid < 128+HH)  creg = c0[BB * HH + b * HH + (tid - 128)];

    __syncthreads();

    // t: layer0 processes step t, layer1 processes step t-1 (wavefront)
    for (int t = 0; t <= SS; t++) {
        if (t < SS && tid < 120) {
            z0s[tid] = dot_step(xs + t * 32, h0s, wi, wh, bj);
        } else if (t >= 1 && tid >= 128 && tid < 248) {
            z1s[tid - 128] = dot_step(y0s, h1s, wi, wh, bj);
        }
        __syncthreads();
        if (t < SS && tid < HH) {
            float ig = fsig(z0s[tid]);
            float fg = fsig(z0s[30 + tid]);
            float gg = ftanh(z0s[60 + tid]);
            float og = fsig(z0s[90 + tid]);
            creg = fg * creg + ig * gg;
            float hh = og * ftanh(creg);
            h0s[tid] = hh;
            y0s[tid] = hh;
        } else if (t >= 1 && tid >= 128 && tid < 128 + HH) {
            int u = tid - 128;
            float ig = fsig(z1s[u]);
            float fg = fsig(z1s[30 + u]);
            float gg = ftanh(z1s[60 + u]);
            float og = fsig(z1s[90 + u]);
            creg = fg * creg + ig * gg;
            float hh = og * ftanh(creg);
            h1s[u] = hh;
            rnn_out[((size_t)b * SS + (t - 1)) * HH + u] = hh;
        }
        __syncthreads();
    }
}

// ---------------- output GEMM: [131072,30] @ [30,512] + bias ----------------
#define OG_TM 64
#define OG_TN 256

__global__ __launch_bounds__(256)
void out_kernel(const float* __restrict__ rnn, const float* __restrict__ Wout,
                const float* __restrict__ bout, float* __restrict__ dorsal)
{
    __shared__ __align__(16) float ws[HH][OG_TN];
    __shared__ __align__(16) float ins[HH][OG_TM];

    const int tid = threadIdx.x;
    const int cb  = (blockIdx.x & 1) * OG_TN;
    const size_t rowBase = (size_t)(blockIdx.x >> 1) * OG_TM;

    for (int i = tid; i < HH * OG_TN; i += 256) {
        int k = i >> 8, c = i & 255;
        ws[k][c] = Wout[(size_t)k * N_OUT + cb + c];
    }
    for (int i = tid; i < OG_TM * HH; i += 256) {
        int r = i / HH, k = i % HH;
        ins[k][r] = rnn[(rowBase + r) * HH + k];
    }

    const int rg = tid >> 5;     // 0..7
    const int cg = tid & 31;     // 0..31
    const int r0 = rg * 8, c0 = cg * 8;

    float bv[8];
    #pragma unroll
    for (int j = 0; j < 8; j++) bv[j] = bout[cb + c0 + j];
    float acc[8][8];
    #pragma unroll
    for (int i = 0; i < 8; i++)
        #pragma unroll
        for (int j = 0; j < 8; j++) acc[i][j] = bv[j];

    __syncthreads();

    #pragma unroll
    for (int k = 0; k < HH; k++) {
        float4 i0 = *(const float4*)&ins[k][r0];
        float4 i1 = *(const float4*)&ins[k][r0 + 4];
        float4 w0 = *(const float4*)&ws[k][c0];
        float4 w1 = *(const float4*)&ws[k][c0 + 4];
        float iv[8] = {i0.x, i0.y, i0.z, i0.w, i1.x, i1.y, i1.z, i1.w};
        float wv[8] = {w0.x, w0.y, w0.z, w0.w, w1.x, w1.y, w1.z, w1.w};
        #pragma unroll
        for (int i = 0; i < 8; i++)
            #pragma unroll
            for (int j = 0; j < 8; j++) acc[i][j] += iv[i] * wv[j];
    }

    #pragma unroll
    for (int i = 0; i < 8; i++) {
        size_t row = rowBase + r0 + i;
        float4* dp = (float4*)&dorsal[row * N_OUT + cb + c0];
        dp[0] = make_float4(acc[i][0], acc[i][1], acc[i][2], acc[i][3]);
        dp[1] = make_float4(acc[i][4], acc[i][5], acc[i][6], acc[i][7]);
    }
}

// ---------------- launch ----------------
extern "C" void kernel_launch(void* const* d_in, const int* in_sizes, int n_in,
                              void* d_out, int out_size)
{
    const float* x     = (const float*)d_in[0];
    const float* h0    = (const float*)d_in[1];
    const float* c0    = (const float*)d_in[2];
    const float* W1    = (const float*)d_in[3];
    const float* b1    = (const float*)d_in[4];
    const float* Wih0  = (const float*)d_in[5];
    const float* Whh0  = (const float*)d_in[6];
    const float* bias0 = (const float*)d_in[7];
    const float* Wih1  = (const float*)d_in[8];
    const float* Whh1  = (const float*)d_in[9];
    const float* bias1 = (const float*)d_in[10];
    const float* Wout  = (const float*)d_in[11];
    const float* bout  = (const float*)d_in[12];

    float* out    = (float*)d_out;
    float* dorsal = out;                                   // [B,S,512]
    float* rnn    = out + (size_t)ROWS * N_OUT;            // [B,S,30]

    cudaFuncSetAttribute(lstm_kernel, cudaFuncAttributeMaxDynamicSharedMemorySize,
                         LSTM_SMEM_BYTES);

    fc1_kernel<<<ROWS / FC1_TM, FC1_THREADS>>>(x, W1, b1);
    bn_stats_kernel<<<1, 32>>>();
    lstm_kernel<<<BB, LSTM_THREADS, LSTM_SMEM_BYTES>>>(h0, c0, Wih0, Whh0, bias0,
                                                       Wih1, Whh1, bias1, rnn);
    out_kernel<<<(ROWS / OG_TM) * 2, 256>>>(rnn, Wout, bout, dorsal);
}